// round 12
// baseline (speedup 1.0000x reference)
#include <cuda_runtime.h>
#include <cstdint>

// MiniBatchDiscrimination: out = concat(x, o_b)
//   m = x @ T -> [B, F, K]  (g_m2[f][b][k])
//   norm[i,j,f] = sum_k |m[i,f,k]-m[j,f,k]|;  o_b[j,f] = sum_i exp(-norm) - 1
// Per-term fp32 absorption: (1+ex)-1 == +0.0 exactly when ex <= 2^-24, i.e.
// norm >= 16.64. bound <= norm, so pairs filtered at bound >= 18 are
// guaranteed-absorbed; survivors get exact fp32 norm+exp+absorb, atomicAdd
// into out directly (no final pass; out's o_b region pre-zeroed by gemm).
// Filter: 4-group L1 lower bound over i<j, COMPLEMENTARY-PAIRED j-chunks
// (block p handles jc=p and jc=15-p -> uniform work, fixes R11's occ 27%).
// GEMM: tf32 mma.sync 1-pass (R10-validated), 512 thr = 4 in-CTA K-split
// quarters, per-quarter double buffering, grid 128.
// NOTE (R5): no __threadfence fusion — CCTL.IVALL cost ~28us.
#define B_SZ   512
#define IN_F   512
#define OUT_F  64
#define K_DIMS 16
#define NCOL   1024
#define OUT_W  576

#define NJC    16
#define QCAP   512
#define THRESH 18.0f

// per-quarter smem (words): Ah|Bh, double buffered
#define AW    36
#define BW    72
#define ASZ   (64 * AW)                       // 2304
#define BSZ   (32 * BW)                       // 2304
#define BUF1  (ASZ + BSZ)                     // 4608 words = 18432 B
#define QWORDS (2 * BUF1)                     // 9216 words per quarter
#define GEMM_SMEM_BYTES (4 * QWORDS * 4)      // 147456 B

__device__ float g_m2[OUT_F * B_SZ * K_DIMS];   // [f][b][k]  2 MB
__device__ float g_g4[OUT_F * B_SZ * 4];        // 4-group sums, 0.5 MB

// ---------------- tf32 helpers (sm_80-level PTX, valid on sm_100) ----------
__device__ __forceinline__ uint32_t f2tf32(float x) {
    uint32_t r;
    asm("cvt.rna.tf32.f32 %0, %1;" : "=r"(r) : "f"(x));
    return r;
}
__device__ __forceinline__ void mma8(float (&c)[4], const uint32_t (&a)[4],
                                     const uint32_t (&b)[2]) {
    asm volatile("mma.sync.aligned.m16n8k8.row.col.f32.tf32.tf32.f32 "
                 "{%0,%1,%2,%3}, {%4,%5,%6,%7}, {%8,%9}, {%0,%1,%2,%3};"
                 : "+f"(c[0]), "+f"(c[1]), "+f"(c[2]), "+f"(c[3])
                 : "r"(a[0]), "r"(a[1]), "r"(a[2]), "r"(a[3]),
                   "r"(b[0]), "r"(b[1]));
}

// ---------------------------------------------------------------------------
// Kernel 1: C[512,1024] = X @ T, tf32 1-pass. 512 threads = 4 quarters of
// 128 (qid = t>>7); quarter q covers K [q*128, q*128+128) in 4 chunks of 32,
// double-buffered. Quarters 1-3 dump accs to idle smem; quarter 0 reduces,
// writes g_m2 transposed + g_g4 group sums. Also zeroes out's o_b region.
// ---------------------------------------------------------------------------
__global__ void __launch_bounds__(512) gemm_tc(const float* __restrict__ X,
                                               const float* __restrict__ T,
                                               float* __restrict__ out) {
    extern __shared__ uint32_t sm[];

    const int t = threadIdx.x;
    const int qid = t >> 7, ts = t & 127;
    const int w = ts >> 5, l = ts & 31;
    const int n0 = blockIdx.x * 64, m0 = blockIdx.y * 64;
    const int kb = qid * 128;
    const int wm0 = (w & 1) * 32, wn0 = (w >> 1) * 32;
    const int g = l >> 2, tg = l & 3;
    uint32_t* qbase = sm + qid * QWORDS;

    // zero out's o_b region (32768 floats over first 64 CTAs)
    {
        int cta = blockIdx.y * 16 + blockIdx.x;   // 0..127
        if (cta < 64) {
            int idx = cta * 512 + t;
            out[(idx >> 6) * OUT_W + IN_F + (idx & 63)] = 0.f;
        }
    }

    float acc[2][4][4];
#pragma unroll
    for (int mf = 0; mf < 2; ++mf)
#pragma unroll
        for (int nf = 0; nf < 4; ++nf)
#pragma unroll
            for (int q = 0; q < 4; ++q) acc[mf][nf][q] = 0.f;

    float4 ap[4], bp[4];
#define LOADAB(kk)                                                            \
    _Pragma("unroll") for (int i = 0; i < 4; ++i) {                           \
        int idx4 = ts + i * 128;                                              \
        int ra = idx4 >> 3, ca = idx4 & 7;                                    \
        ap[i] = *(const float4*)&X[(m0 + ra) * IN_F + (kk) + ca * 4];         \
        int rb = idx4 >> 4, cb = idx4 & 15;                                   \
        bp[i] = *(const float4*)&T[((kk) + rb) * NCOL + n0 + cb * 4];         \
    }

#define CVTSTORE(base)                                                        \
    _Pragma("unroll") for (int i = 0; i < 4; ++i) {                           \
        uint32_t* Ah_ = (base); uint32_t* Bh_ = (base) + ASZ;                 \
        int idx4 = ts + i * 128;                                              \
        int ra = idx4 >> 3, ca = idx4 & 7;                                    \
        float4 v = ap[i];                                                     \
        *(uint4*)&Ah_[ra * AW + ca * 4] = make_uint4(                         \
            f2tf32(v.x), f2tf32(v.y), f2tf32(v.z), f2tf32(v.w));              \
        int rb = idx4 >> 4, cb = idx4 & 15;                                   \
        float4 u = bp[i];                                                     \
        *(uint4*)&Bh_[rb * BW + cb * 4] = make_uint4(                         \
            f2tf32(u.x), f2tf32(u.y), f2tf32(u.z), f2tf32(u.w));              \
    }

    LOADAB(kb);
    CVTSTORE(qbase);
    __syncthreads();

    for (int c = 0; c < 4; ++c) {
        const bool more = (c < 3);
        uint32_t* cb_ = qbase + (c & 1) * BUF1;
        uint32_t* nb_ = qbase + ((c + 1) & 1) * BUF1;

        if (more) LOADAB(kb + (c + 1) * 32);   // LDG hidden under MMA

        uint32_t* Ah_ = cb_;
        uint32_t* Bh_ = cb_ + ASZ;

#pragma unroll
        for (int s = 0; s < 4; ++s) {
            const int k8 = s * 8;
            uint32_t ah[2][4], bh[4][2];
#pragma unroll
            for (int mf = 0; mf < 2; ++mf) {
                int r0 = wm0 + mf * 16 + g;
                ah[mf][0] = Ah_[r0 * AW + k8 + tg];
                ah[mf][1] = Ah_[(r0 + 8) * AW + k8 + tg];
                ah[mf][2] = Ah_[r0 * AW + k8 + tg + 4];
                ah[mf][3] = Ah_[(r0 + 8) * AW + k8 + tg + 4];
            }
#pragma unroll
            for (int nf = 0; nf < 4; ++nf) {
                int c0 = wn0 + nf * 8 + g;
                bh[nf][0] = Bh_[(k8 + tg) * BW + c0];
                bh[nf][1] = Bh_[(k8 + tg + 4) * BW + c0];
            }
#pragma unroll
            for (int mf = 0; mf < 2; ++mf)
#pragma unroll
                for (int nf = 0; nf < 4; ++nf) mma8(acc[mf][nf], ah[mf], bh[nf]);
        }

        if (more) CVTSTORE(nb_);               // write other buffer
        __syncthreads();
    }

    // ---- in-CTA K reduction through smem (quarters 1-3 -> quarter 0) ----
    if (qid != 0) {
        float* red = (float*)qbase;            // own region, now idle
        int r = 0;
#pragma unroll
        for (int mf = 0; mf < 2; ++mf)
#pragma unroll
            for (int nf = 0; nf < 4; ++nf)
#pragma unroll
                for (int q = 0; q < 4; ++q)
                    red[(r++) * 128 + ts] = acc[mf][nf][q];
    }
    __syncthreads();
    if (qid == 0) {
#pragma unroll
        for (int qq = 1; qq < 4; ++qq) {
            const float* red = (const float*)(sm + qq * QWORDS);
            int r = 0;
#pragma unroll
            for (int mf = 0; mf < 2; ++mf)
#pragma unroll
                for (int nf = 0; nf < 4; ++nf)
#pragma unroll
                    for (int q = 0; q < 4; ++q)
                        acc[mf][nf][q] += red[(r++) * 128 + ts];
        }
        // epilogue: c0:(row,2tg) c1:(row,2tg+1) c2:(row+8,2tg) c3:(row+8,+1)
#pragma unroll
        for (int mf = 0; mf < 2; ++mf)
#pragma unroll
            for (int nf = 0; nf < 4; ++nf) {
                int row = m0 + wm0 + mf * 16 + g;
                int col = n0 + wn0 + nf * 8 + 2 * tg;
                int f = col >> 4, k = col & 15;
                float* c = acc[mf][nf];
                *(float2*)&g_m2[f * (B_SZ * K_DIMS) + row * K_DIMS + k] =
                    make_float2(c[0], c[1]);
                *(float2*)&g_m2[f * (B_SZ * K_DIMS) + (row + 8) * K_DIMS + k] =
                    make_float2(c[2], c[3]);
                // group sums: pair within thread, then pair tg^1 (same row)
                float s0 = c[0] + c[1], s1 = c[2] + c[3];
                s0 += __shfl_xor_sync(0xffffffffu, s0, 1);
                s1 += __shfl_xor_sync(0xffffffffu, s1, 1);
                if ((tg & 1) == 0) {
                    int grp = ((nf & 1) << 1) | (tg >> 1);
                    g_g4[f * (B_SZ * 4) + row * 4 + grp] = s0;
                    g_g4[f * (B_SZ * 4) + (row + 8) * 4 + grp] = s1;
                }
            }
    }
}

// ---------------------------------------------------------------------------
// Kernel 2: bound filter (triangular i<j) + exact exp for survivors with
// per-term fp32 absorption, atomicAdd straight into out (no final pass).
// Block (f, p): processes j-chunks jc=p AND jc=15-p (complementary pairing
// -> uniform work across all 512 blocks). 128 thr = 32 j-lanes x 4 i-warps.
// Stages only group sums (16B/row); survivors read m rows from L2.
// ---------------------------------------------------------------------------
__global__ void __launch_bounds__(128) boundexp(const float* __restrict__ X,
                                                float* __restrict__ out) {
    __shared__ float sg[B_SZ * 4];                 // [row][group]
    __shared__ unsigned short q[4][QCAP];          // survivor queues

    const int f = blockIdx.x, p = blockIdx.y;      // p in [0,8)
    const int tid = threadIdx.x, jl = tid & 31, ig = tid >> 5;
    const int stage_rows = (16 - p) * 32;          // covers both chunks

    // folded x-copy: 65536 float4s over 512 blocks
    {
        int base4 = (f * 8 + p) * 128;
        int idx4 = base4 + tid;
        int b = idx4 >> 7, c4 = idx4 & 127;
        ((float4*)(out + b * OUT_W))[c4] = ((const float4*)(X + b * IN_F))[c4];
    }
    {
        const float4* src = (const float4*)(g_g4 + f * (B_SZ * 4));
        for (int idx = tid; idx < stage_rows; idx += 128)
            ((float4*)sg)[idx] = src[idx];
    }
    __syncthreads();

    const unsigned lt = (1u << jl) - 1u;
    const float4* mf4 = (const float4*)(g_m2 + f * (B_SZ * K_DIMS));

#pragma unroll
    for (int cc = 0; cc < 2; ++cc) {
        const int jc = cc ? (15 - p) : p;
        const int imax = (jc + 1) * 32;
        const int j = jc * 32 + jl;
        const float4 h = ((const float4*)sg)[j];
        int cnt = 0;

#pragma unroll 4
        for (int i = ig; i < imax; i += 4) {
            float4 a = ((const float4*)sg)[i];     // broadcast LDS.128
            float bnd = (fabsf(a.x - h.x) + fabsf(a.y - h.y)) +
                        (fabsf(a.z - h.z) + fabsf(a.w - h.w));
            bool keep = (bnd < THRESH) && (i < j);
            unsigned bal = __ballot_sync(0xffffffffu, keep);
            if (bal) {
                int ofs = cnt + __popc(bal & lt);
                if (keep && ofs < QCAP)
                    q[ig][ofs] = (unsigned short)((i << 5) | jl);
                cnt += __popc(bal);
            }
        }
        __syncwarp();

        const int n = min(cnt, QCAP);              // warp-uniform
        for (int u = jl; u < n; u += 32) {
            unsigned e = q[ig][u];
            int i = e >> 5;
            int jj = jc * 32 + (e & 31);
            const float4* mi = mf4 + i * 4;        // L2-resident
            const float4* mj = mf4 + jj * 4;
            float norm = 0.f;
#pragma unroll
            for (int pp = 0; pp < 4; ++pp) {
                float4 a = mi[pp], b = mj[pp];
                norm += (fabsf(a.x - b.x) + fabsf(a.y - b.y)) +
                        (fabsf(a.z - b.z) + fabsf(a.w - b.w));
            }
            // per-term fp32 absorption vs self-term 1.0: ex <= 2^-24 ->
            // exactly +0.0f (deterministic adds), matching reference.
            float ex = __expf(-norm);
            float exa = __fadd_rn(__fadd_rn(1.0f, ex), -1.0f);
            atomicAdd(&out[jj * OUT_W + IN_F + f], exa);   // both sides
            atomicAdd(&out[i * OUT_W + IN_F + f], exa);
        }
        __syncwarp();                              // queue reuse safety
    }
}

// ---------------------------------------------------------------------------
extern "C" void kernel_launch(void* const* d_in, const int* in_sizes, int n_in,
                              void* d_out, int out_size) {
    const float* X = (const float*)d_in[0];   // [512, 512]
    const float* T = (const float*)d_in[1];   // [512, 64, 16]
    float* out = (float*)d_out;               // [512, 576]

    // host-side attribute set (not a stream op; capture-safe, deterministic)
    cudaFuncSetAttribute(gemm_tc, cudaFuncAttributeMaxDynamicSharedMemorySize,
                         GEMM_SMEM_BYTES);

    gemm_tc<<<dim3(16, 8), 512, GEMM_SMEM_BYTES>>>(X, T, out);
    boundexp<<<dim3(OUT_F, 8), 128>>>(X, out);
}

// round 13
// speedup vs baseline: 1.0607x; 1.0607x over previous
#include <cuda_runtime.h>
#include <cstdint>

// MiniBatchDiscrimination: out = concat(x, o_b)
//   m = x @ T -> [B, F, K]  (g_m2[f][b][k])
//   norm[i,j,f] = sum_k |m[i,f,k]-m[j,f,k]|;  o_b[j,f] = sum_i exp(-norm) - 1
// Per-term fp32 absorption: (1+ex)-1 == +0.0 exactly when ex <= 2^-24, i.e.
// norm >= 16.64. bound <= norm, so pairs filtered at bound >= 18 are
// guaranteed-absorbed; survivors get exact fp32 norm+exp+absorb, atomicAdd
// into out directly (out's o_b region pre-zeroed by gemm).
// Filter: 4-group L1 lower bound over i<j. R12 lesson: ballot/popc queue
// bookkeeping dominated the loop -> BALLOT-FREE two-phase: phase 1 packs
// keep-bits into per-thread registers (pure FADD/FSETP/LOP, deep ILP);
// phase 2 bit-scans (~1 survivor/thread) and handles them inline.
// GEMM: tf32 mma.sync 1-pass (R10-validated), 512 thr = 4 in-CTA K-split
// quarters, per-quarter double buffering, grid 128.
// NOTE (R5): no __threadfence fusion — CCTL.IVALL cost ~28us.
#define B_SZ   512
#define IN_F   512
#define OUT_F  64
#define K_DIMS 16
#define NCOL   1024
#define OUT_W  576

#define THRESH 18.0f

// per-quarter smem (words): Ah|Bh, double buffered
#define AW    36
#define BW    72
#define ASZ   (64 * AW)                       // 2304
#define BSZ   (32 * BW)                       // 2304
#define BUF1  (ASZ + BSZ)                     // 4608 words = 18432 B
#define QWORDS (2 * BUF1)                     // 9216 words per quarter
#define GEMM_SMEM_BYTES (4 * QWORDS * 4)      // 147456 B

__device__ float g_m2[OUT_F * B_SZ * K_DIMS];   // [f][b][k]  2 MB
__device__ float g_g4[OUT_F * B_SZ * 4];        // 4-group sums, 0.5 MB

// ---------------- tf32 helpers (sm_80-level PTX, valid on sm_100) ----------
__device__ __forceinline__ uint32_t f2tf32(float x) {
    uint32_t r;
    asm("cvt.rna.tf32.f32 %0, %1;" : "=r"(r) : "f"(x));
    return r;
}
__device__ __forceinline__ void mma8(float (&c)[4], const uint32_t (&a)[4],
                                     const uint32_t (&b)[2]) {
    asm volatile("mma.sync.aligned.m16n8k8.row.col.f32.tf32.tf32.f32 "
                 "{%0,%1,%2,%3}, {%4,%5,%6,%7}, {%8,%9}, {%0,%1,%2,%3};"
                 : "+f"(c[0]), "+f"(c[1]), "+f"(c[2]), "+f"(c[3])
                 : "r"(a[0]), "r"(a[1]), "r"(a[2]), "r"(a[3]),
                   "r"(b[0]), "r"(b[1]));
}

// ---------------------------------------------------------------------------
// Kernel 1: C[512,1024] = X @ T, tf32 1-pass. 512 threads = 4 quarters of
// 128 (qid = t>>7); quarter q covers K [q*128, q*128+128) in 4 chunks of 32,
// double-buffered. Quarters 1-3 dump accs to idle smem; quarter 0 reduces,
// writes g_m2 transposed + g_g4 group sums. Also zeroes out's o_b region.
// ---------------------------------------------------------------------------
__global__ void __launch_bounds__(512) gemm_tc(const float* __restrict__ X,
                                               const float* __restrict__ T,
                                               float* __restrict__ out) {
    extern __shared__ uint32_t sm[];

    const int t = threadIdx.x;
    const int qid = t >> 7, ts = t & 127;
    const int w = ts >> 5, l = ts & 31;
    const int n0 = blockIdx.x * 64, m0 = blockIdx.y * 64;
    const int kb = qid * 128;
    const int wm0 = (w & 1) * 32, wn0 = (w >> 1) * 32;
    const int g = l >> 2, tg = l & 3;
    uint32_t* qbase = sm + qid * QWORDS;

    // zero out's o_b region (32768 floats over first 64 CTAs)
    {
        int cta = blockIdx.y * 16 + blockIdx.x;   // 0..127
        if (cta < 64) {
            int idx = cta * 512 + t;
            out[(idx >> 6) * OUT_W + IN_F + (idx & 63)] = 0.f;
        }
    }

    float acc[2][4][4];
#pragma unroll
    for (int mf = 0; mf < 2; ++mf)
#pragma unroll
        for (int nf = 0; nf < 4; ++nf)
#pragma unroll
            for (int q = 0; q < 4; ++q) acc[mf][nf][q] = 0.f;

    float4 ap[4], bp[4];
#define LOADAB(kk)                                                            \
    _Pragma("unroll") for (int i = 0; i < 4; ++i) {                           \
        int idx4 = ts + i * 128;                                              \
        int ra = idx4 >> 3, ca = idx4 & 7;                                    \
        ap[i] = *(const float4*)&X[(m0 + ra) * IN_F + (kk) + ca * 4];         \
        int rb = idx4 >> 4, cb = idx4 & 15;                                   \
        bp[i] = *(const float4*)&T[((kk) + rb) * NCOL + n0 + cb * 4];         \
    }

#define CVTSTORE(base)                                                        \
    _Pragma("unroll") for (int i = 0; i < 4; ++i) {                           \
        uint32_t* Ah_ = (base); uint32_t* Bh_ = (base) + ASZ;                 \
        int idx4 = ts + i * 128;                                              \
        int ra = idx4 >> 3, ca = idx4 & 7;                                    \
        float4 v = ap[i];                                                     \
        *(uint4*)&Ah_[ra * AW + ca * 4] = make_uint4(                         \
            f2tf32(v.x), f2tf32(v.y), f2tf32(v.z), f2tf32(v.w));              \
        int rb = idx4 >> 4, cb = idx4 & 15;                                   \
        float4 u = bp[i];                                                     \
        *(uint4*)&Bh_[rb * BW + cb * 4] = make_uint4(                         \
            f2tf32(u.x), f2tf32(u.y), f2tf32(u.z), f2tf32(u.w));              \
    }

    LOADAB(kb);
    CVTSTORE(qbase);
    __syncthreads();

    for (int c = 0; c < 4; ++c) {
        const bool more = (c < 3);
        uint32_t* cb_ = qbase + (c & 1) * BUF1;
        uint32_t* nb_ = qbase + ((c + 1) & 1) * BUF1;

        if (more) LOADAB(kb + (c + 1) * 32);   // LDG hidden under MMA

        uint32_t* Ah_ = cb_;
        uint32_t* Bh_ = cb_ + ASZ;

#pragma unroll
        for (int s = 0; s < 4; ++s) {
            const int k8 = s * 8;
            uint32_t ah[2][4], bh[4][2];
#pragma unroll
            for (int mf = 0; mf < 2; ++mf) {
                int r0 = wm0 + mf * 16 + g;
                ah[mf][0] = Ah_[r0 * AW + k8 + tg];
                ah[mf][1] = Ah_[(r0 + 8) * AW + k8 + tg];
                ah[mf][2] = Ah_[r0 * AW + k8 + tg + 4];
                ah[mf][3] = Ah_[(r0 + 8) * AW + k8 + tg + 4];
            }
#pragma unroll
            for (int nf = 0; nf < 4; ++nf) {
                int c0 = wn0 + nf * 8 + g;
                bh[nf][0] = Bh_[(k8 + tg) * BW + c0];
                bh[nf][1] = Bh_[(k8 + tg + 4) * BW + c0];
            }
#pragma unroll
            for (int mf = 0; mf < 2; ++mf)
#pragma unroll
                for (int nf = 0; nf < 4; ++nf) mma8(acc[mf][nf], ah[mf], bh[nf]);
        }

        if (more) CVTSTORE(nb_);               // write other buffer
        __syncthreads();
    }

    // ---- in-CTA K reduction through smem (quarters 1-3 -> quarter 0) ----
    if (qid != 0) {
        float* red = (float*)qbase;            // own region, now idle
        int r = 0;
#pragma unroll
        for (int mf = 0; mf < 2; ++mf)
#pragma unroll
            for (int nf = 0; nf < 4; ++nf)
#pragma unroll
                for (int q = 0; q < 4; ++q)
                    red[(r++) * 128 + ts] = acc[mf][nf][q];
    }
    __syncthreads();
    if (qid == 0) {
#pragma unroll
        for (int qq = 1; qq < 4; ++qq) {
            const float* red = (const float*)(sm + qq * QWORDS);
            int r = 0;
#pragma unroll
            for (int mf = 0; mf < 2; ++mf)
#pragma unroll
                for (int nf = 0; nf < 4; ++nf)
#pragma unroll
                    for (int q = 0; q < 4; ++q)
                        acc[mf][nf][q] += red[(r++) * 128 + ts];
        }
        // epilogue: c0:(row,2tg) c1:(row,2tg+1) c2:(row+8,2tg) c3:(row+8,+1)
#pragma unroll
        for (int mf = 0; mf < 2; ++mf)
#pragma unroll
            for (int nf = 0; nf < 4; ++nf) {
                int row = m0 + wm0 + mf * 16 + g;
                int col = n0 + wn0 + nf * 8 + 2 * tg;
                int f = col >> 4, k = col & 15;
                float* c = acc[mf][nf];
                *(float2*)&g_m2[f * (B_SZ * K_DIMS) + row * K_DIMS + k] =
                    make_float2(c[0], c[1]);
                *(float2*)&g_m2[f * (B_SZ * K_DIMS) + (row + 8) * K_DIMS + k] =
                    make_float2(c[2], c[3]);
                // group sums: pair within thread, then pair tg^1 (same row)
                float s0 = c[0] + c[1], s1 = c[2] + c[3];
                s0 += __shfl_xor_sync(0xffffffffu, s0, 1);
                s1 += __shfl_xor_sync(0xffffffffu, s1, 1);
                if ((tg & 1) == 0) {
                    int grp = ((nf & 1) << 1) | (tg >> 1);
                    g_g4[f * (B_SZ * 4) + row * 4 + grp] = s0;
                    g_g4[f * (B_SZ * 4) + (row + 8) * 4 + grp] = s1;
                }
            }
    }
}

// ---------------------------------------------------------------------------
// Kernel 2: ballot-free bound filter + inline survivor handling.
// Block (f, p): j-chunks jc=p and jc=15-p (uniform work). 128 thr = 32
// j-lanes x 4 i-warps. Phase 1: keep-bits -> registers (no sync ops).
// Phase 2: per-thread bit-scan, exact norm from L2, fp32-absorbed atomicAdd
// straight into out (all adds are bitwise +0.0 in practice).
// ---------------------------------------------------------------------------
__global__ void __launch_bounds__(128) boundexp(const float* __restrict__ X,
                                                float* __restrict__ out) {
    __shared__ float sg[B_SZ * 4];                 // [row][group]

    const int f = blockIdx.x, p = blockIdx.y;      // p in [0,8)
    const int tid = threadIdx.x, jl = tid & 31, ig = tid >> 5;
    const int stage_rows = (16 - p) * 32;          // covers both chunks

    // folded x-copy: 65536 float4s over 512 blocks
    {
        int idx4 = (f * 8 + p) * 128 + tid;
        int b = idx4 >> 7, c4 = idx4 & 127;
        ((float4*)(out + b * OUT_W))[c4] = ((const float4*)(X + b * IN_F))[c4];
    }
    {
        const float4* src = (const float4*)(g_g4 + f * (B_SZ * 4));
        for (int idx = tid; idx < stage_rows; idx += 128)
            ((float4*)sg)[idx] = src[idx];
    }
    __syncthreads();

    const float4* mf4 = (const float4*)(g_m2 + f * (B_SZ * K_DIMS));

#pragma unroll
    for (int cc = 0; cc < 2; ++cc) {
        const int jc = cc ? (15 - p) : p;
        const int imax = (jc + 1) * 32;
        const int j = jc * 32 + jl;
        const float4 h = ((const float4*)sg)[j];
        const int nb_max = imax >> 2;              // per-thread eval count

        // ---- phase 1: pack keep-bits (no warp sync ops, deep ILP) ----
        uint32_t mask[4] = {0u, 0u, 0u, 0u};
#pragma unroll 8
        for (int nb = 0; nb < nb_max; ++nb) {
            int i = ig + nb * 4;
            float4 a = ((const float4*)sg)[i];     // broadcast LDS.128
            float bnd = (fabsf(a.x - h.x) + fabsf(a.y - h.y)) +
                        (fabsf(a.z - h.z) + fabsf(a.w - h.w));
            if ((bnd < THRESH) && (i < j))
                mask[nb >> 5] |= 1u << (nb & 31);
        }

        // ---- phase 2: per-thread survivors (expected ~1/thread) ----
#pragma unroll
        for (int wq = 0; wq < 4; ++wq) {
            uint32_t msk = mask[wq];
            while (msk) {
                int b = __ffs(msk) - 1;
                msk &= msk - 1;
                int i = ig + ((wq << 5) + b) * 4;
                const float4* mi = mf4 + i * 4;    // L2-resident
                const float4* mj = mf4 + j * 4;
                float norm = 0.f;
#pragma unroll
                for (int pp = 0; pp < 4; ++pp) {
                    float4 a = mi[pp], bb = mj[pp];
                    norm += (fabsf(a.x - bb.x) + fabsf(a.y - bb.y)) +
                            (fabsf(a.z - bb.z) + fabsf(a.w - bb.w));
                }
                // fp32 absorption vs self-term 1.0: ex <= 2^-24 -> +0.0f
                float ex = __expf(-norm);
                float exa = __fadd_rn(__fadd_rn(1.0f, ex), -1.0f);
                atomicAdd(&out[j * OUT_W + IN_F + f], exa);   // both sides
                atomicAdd(&out[i * OUT_W + IN_F + f], exa);
            }
        }
    }
}

// ---------------------------------------------------------------------------
extern "C" void kernel_launch(void* const* d_in, const int* in_sizes, int n_in,
                              void* d_out, int out_size) {
    const float* X = (const float*)d_in[0];   // [512, 512]
    const float* T = (const float*)d_in[1];   // [512, 64, 16]
    float* out = (float*)d_out;               // [512, 576]

    // host-side attribute set (not a stream op; capture-safe, deterministic)
    cudaFuncSetAttribute(gemm_tc, cudaFuncAttributeMaxDynamicSharedMemorySize,
                         GEMM_SMEM_BYTES);

    gemm_tc<<<dim3(16, 8), 512, GEMM_SMEM_BYTES>>>(X, T, out);
    boundexp<<<dim3(OUT_F, 8), 128>>>(X, out);
}

// round 14
// speedup vs baseline: 1.0954x; 1.0328x over previous
#include <cuda_runtime.h>
#include <cstdint>

// MiniBatchDiscrimination: out = concat(x, o_b)
//   m = x @ T -> [B, F, K]  (g_m2[f][b][k])
//   norm[i,j,f] = sum_k |m[i,f,k]-m[j,f,k]|;  o_b[j,f] = sum_i exp(-norm) - 1
// Per-term fp32 absorption: (1+ex)-1 == +0.0 exactly when ex <= 2^-24, i.e.
// norm >= 16.64. bound <= norm, so pairs filtered at bound >= 18 are
// guaranteed-absorbed; survivors get exact fp32 norm+exp+absorb, atomicAdd
// into out directly (out's o_b region pre-zeroed by gemm).
// R13 lesson: mask[nb>>5] runtime indexing spilled to LOCAL MEMORY and
// serialized the filter loop (~60cyc/iter). Now: scalar uint32 mask per
// 32-iteration chunk (register-resident), survivors inline per chunk, and
// the i<j test hoisted to a once-per-chunk bitmask. 256 thr/block (8
// i-groups) doubles occupancy (R13: 19.4%).
// GEMM: tf32 mma.sync 1-pass (R10-validated), 512 thr = 4 in-CTA K-split
// quarters, per-quarter double buffering, grid 128.
// NOTE (R5): no __threadfence fusion — CCTL.IVALL cost ~28us.
#define B_SZ   512
#define IN_F   512
#define OUT_F  64
#define K_DIMS 16
#define NCOL   1024
#define OUT_W  576

#define THRESH 18.0f

// per-quarter smem (words): Ah|Bh, double buffered
#define AW    36
#define BW    72
#define ASZ   (64 * AW)                       // 2304
#define BSZ   (32 * BW)                       // 2304
#define BUF1  (ASZ + BSZ)                     // 4608 words = 18432 B
#define QWORDS (2 * BUF1)                     // 9216 words per quarter
#define GEMM_SMEM_BYTES (4 * QWORDS * 4)      // 147456 B

__device__ float g_m2[OUT_F * B_SZ * K_DIMS];   // [f][b][k]  2 MB
__device__ float g_g4[OUT_F * B_SZ * 4];        // 4-group sums, 0.5 MB

// ---------------- tf32 helpers (sm_80-level PTX, valid on sm_100) ----------
__device__ __forceinline__ uint32_t f2tf32(float x) {
    uint32_t r;
    asm("cvt.rna.tf32.f32 %0, %1;" : "=r"(r) : "f"(x));
    return r;
}
__device__ __forceinline__ void mma8(float (&c)[4], const uint32_t (&a)[4],
                                     const uint32_t (&b)[2]) {
    asm volatile("mma.sync.aligned.m16n8k8.row.col.f32.tf32.tf32.f32 "
                 "{%0,%1,%2,%3}, {%4,%5,%6,%7}, {%8,%9}, {%0,%1,%2,%3};"
                 : "+f"(c[0]), "+f"(c[1]), "+f"(c[2]), "+f"(c[3])
                 : "r"(a[0]), "r"(a[1]), "r"(a[2]), "r"(a[3]),
                   "r"(b[0]), "r"(b[1]));
}

// ---------------------------------------------------------------------------
// Kernel 1: C[512,1024] = X @ T, tf32 1-pass. 512 threads = 4 quarters of
// 128 (qid = t>>7); quarter q covers K [q*128, q*128+128) in 4 chunks of 32,
// double-buffered. Quarters 1-3 dump accs to idle smem; quarter 0 reduces,
// writes g_m2 transposed + g_g4 group sums. Also zeroes out's o_b region.
// ---------------------------------------------------------------------------
__global__ void __launch_bounds__(512) gemm_tc(const float* __restrict__ X,
                                               const float* __restrict__ T,
                                               float* __restrict__ out) {
    extern __shared__ uint32_t sm[];

    const int t = threadIdx.x;
    const int qid = t >> 7, ts = t & 127;
    const int w = ts >> 5, l = ts & 31;
    const int n0 = blockIdx.x * 64, m0 = blockIdx.y * 64;
    const int kb = qid * 128;
    const int wm0 = (w & 1) * 32, wn0 = (w >> 1) * 32;
    const int g = l >> 2, tg = l & 3;
    uint32_t* qbase = sm + qid * QWORDS;

    // zero out's o_b region (32768 floats over first 64 CTAs)
    {
        int cta = blockIdx.y * 16 + blockIdx.x;   // 0..127
        if (cta < 64) {
            int idx = cta * 512 + t;
            out[(idx >> 6) * OUT_W + IN_F + (idx & 63)] = 0.f;
        }
    }

    float acc[2][4][4];
#pragma unroll
    for (int mf = 0; mf < 2; ++mf)
#pragma unroll
        for (int nf = 0; nf < 4; ++nf)
#pragma unroll
            for (int q = 0; q < 4; ++q) acc[mf][nf][q] = 0.f;

    float4 ap[4], bp[4];
#define LOADAB(kk)                                                            \
    _Pragma("unroll") for (int i = 0; i < 4; ++i) {                           \
        int idx4 = ts + i * 128;                                              \
        int ra = idx4 >> 3, ca = idx4 & 7;                                    \
        ap[i] = *(const float4*)&X[(m0 + ra) * IN_F + (kk) + ca * 4];         \
        int rb = idx4 >> 4, cb = idx4 & 15;                                   \
        bp[i] = *(const float4*)&T[((kk) + rb) * NCOL + n0 + cb * 4];         \
    }

#define CVTSTORE(base)                                                        \
    _Pragma("unroll") for (int i = 0; i < 4; ++i) {                           \
        uint32_t* Ah_ = (base); uint32_t* Bh_ = (base) + ASZ;                 \
        int idx4 = ts + i * 128;                                              \
        int ra = idx4 >> 3, ca = idx4 & 7;                                    \
        float4 v = ap[i];                                                     \
        *(uint4*)&Ah_[ra * AW + ca * 4] = make_uint4(                         \
            f2tf32(v.x), f2tf32(v.y), f2tf32(v.z), f2tf32(v.w));              \
        int rb = idx4 >> 4, cb = idx4 & 15;                                   \
        float4 u = bp[i];                                                     \
        *(uint4*)&Bh_[rb * BW + cb * 4] = make_uint4(                         \
            f2tf32(u.x), f2tf32(u.y), f2tf32(u.z), f2tf32(u.w));              \
    }

    LOADAB(kb);
    CVTSTORE(qbase);
    __syncthreads();

    for (int c = 0; c < 4; ++c) {
        const bool more = (c < 3);
        uint32_t* cb_ = qbase + (c & 1) * BUF1;
        uint32_t* nb_ = qbase + ((c + 1) & 1) * BUF1;

        if (more) LOADAB(kb + (c + 1) * 32);   // LDG hidden under MMA

        uint32_t* Ah_ = cb_;
        uint32_t* Bh_ = cb_ + ASZ;

#pragma unroll
        for (int s = 0; s < 4; ++s) {
            const int k8 = s * 8;
            uint32_t ah[2][4], bh[4][2];
#pragma unroll
            for (int mf = 0; mf < 2; ++mf) {
                int r0 = wm0 + mf * 16 + g;
                ah[mf][0] = Ah_[r0 * AW + k8 + tg];
                ah[mf][1] = Ah_[(r0 + 8) * AW + k8 + tg];
                ah[mf][2] = Ah_[r0 * AW + k8 + tg + 4];
                ah[mf][3] = Ah_[(r0 + 8) * AW + k8 + tg + 4];
            }
#pragma unroll
            for (int nf = 0; nf < 4; ++nf) {
                int c0 = wn0 + nf * 8 + g;
                bh[nf][0] = Bh_[(k8 + tg) * BW + c0];
                bh[nf][1] = Bh_[(k8 + tg + 4) * BW + c0];
            }
#pragma unroll
            for (int mf = 0; mf < 2; ++mf)
#pragma unroll
                for (int nf = 0; nf < 4; ++nf) mma8(acc[mf][nf], ah[mf], bh[nf]);
        }

        if (more) CVTSTORE(nb_);               // write other buffer
        __syncthreads();
    }

    // ---- in-CTA K reduction through smem (quarters 1-3 -> quarter 0) ----
    if (qid != 0) {
        float* red = (float*)qbase;            // own region, now idle
        int r = 0;
#pragma unroll
        for (int mf = 0; mf < 2; ++mf)
#pragma unroll
            for (int nf = 0; nf < 4; ++nf)
#pragma unroll
                for (int q = 0; q < 4; ++q)
                    red[(r++) * 128 + ts] = acc[mf][nf][q];
    }
    __syncthreads();
    if (qid == 0) {
#pragma unroll
        for (int qq = 1; qq < 4; ++qq) {
            const float* red = (const float*)(sm + qq * QWORDS);
            int r = 0;
#pragma unroll
            for (int mf = 0; mf < 2; ++mf)
#pragma unroll
                for (int nf = 0; nf < 4; ++nf)
#pragma unroll
                    for (int q = 0; q < 4; ++q)
                        acc[mf][nf][q] += red[(r++) * 128 + ts];
        }
        // epilogue: c0:(row,2tg) c1:(row,2tg+1) c2:(row+8,2tg) c3:(row+8,+1)
#pragma unroll
        for (int mf = 0; mf < 2; ++mf)
#pragma unroll
            for (int nf = 0; nf < 4; ++nf) {
                int row = m0 + wm0 + mf * 16 + g;
                int col = n0 + wn0 + nf * 8 + 2 * tg;
                int f = col >> 4, k = col & 15;
                float* c = acc[mf][nf];
                *(float2*)&g_m2[f * (B_SZ * K_DIMS) + row * K_DIMS + k] =
                    make_float2(c[0], c[1]);
                *(float2*)&g_m2[f * (B_SZ * K_DIMS) + (row + 8) * K_DIMS + k] =
                    make_float2(c[2], c[3]);
                // group sums: pair within thread, then pair tg^1 (same row)
                float s0 = c[0] + c[1], s1 = c[2] + c[3];
                s0 += __shfl_xor_sync(0xffffffffu, s0, 1);
                s1 += __shfl_xor_sync(0xffffffffu, s1, 1);
                if ((tg & 1) == 0) {
                    int grp = ((nf & 1) << 1) | (tg >> 1);
                    g_g4[f * (B_SZ * 4) + row * 4 + grp] = s0;
                    g_g4[f * (B_SZ * 4) + (row + 8) * 4 + grp] = s1;
                }
            }
    }
}

// ---------------------------------------------------------------------------
// Kernel 2: bound filter + inline survivors, scalar-mask chunks.
// Block (f, p): j-chunks jc=p and jc=15-p (uniform work). 256 thr = 32
// j-lanes x 8 i-groups. Filter loop body: LDS.128 + 7 FADD + FSETP + pred
// OR into a SCALAR register mask; i<j applied once per 32-chunk as a
// bitmask. Survivors (exact fp32 norm+exp+absorb) handled inline.
// ---------------------------------------------------------------------------
__global__ void __launch_bounds__(256) boundexp(const float* __restrict__ X,
                                                float* __restrict__ out) {
    __shared__ float sg[B_SZ * 4];                 // [row][group]

    const int f = blockIdx.x, p = blockIdx.y;      // p in [0,8)
    const int tid = threadIdx.x, jl = tid & 31, ig = tid >> 5;  // ig 0..7
    const int stage_rows = (16 - p) * 32;          // covers both chunks

    // folded x-copy: 65536 float4s over 512 blocks
    if (tid < 128) {
        int idx4 = (f * 8 + p) * 128 + tid;
        int b = idx4 >> 7, c4 = idx4 & 127;
        ((float4*)(out + b * OUT_W))[c4] = ((const float4*)(X + b * IN_F))[c4];
    }
    {
        const float4* src = (const float4*)(g_g4 + f * (B_SZ * 4));
        for (int idx = tid; idx < stage_rows; idx += 256)
            ((float4*)sg)[idx] = src[idx];
    }
    __syncthreads();

    const float4* mf4 = (const float4*)(g_m2 + f * (B_SZ * K_DIMS));

#pragma unroll
    for (int cc = 0; cc < 2; ++cc) {
        const int jc = cc ? (15 - p) : p;
        const int imax = (jc + 1) * 32;
        const int j = jc * 32 + jl;
        const float4 h = ((const float4*)sg)[j];
        const int nb_max = imax >> 3;              // i = ig + nb*8
        // i < j  <=>  nb < nb_lim (hoisted out of the hot loop)
        const int nb_lim = (j > ig) ? ((j - ig + 7) >> 3) : 0;

        for (int base = 0; base < nb_max; base += 32) {
            const int lim = min(32, nb_max - base);
            uint32_t msk = 0u;                     // scalar: stays in a reg
#pragma unroll 8
            for (int b = 0; b < lim; ++b) {
                int i = ig + (base + b) * 8;
                float4 a = ((const float4*)sg)[i]; // broadcast LDS.128
                float bnd = (fabsf(a.x - h.x) + fabsf(a.y - h.y)) +
                            (fabsf(a.z - h.z) + fabsf(a.w - h.w));
                if (bnd < THRESH) msk |= 1u << b;
            }
            // apply i<j once per chunk
            int rel = nb_lim - base;
            uint32_t allowed = (rel <= 0) ? 0u
                             : (rel >= 32) ? 0xffffffffu : ((1u << rel) - 1u);
            msk &= allowed;

            while (msk) {                          // expected ~0.3/chunk
                int b = __ffs(msk) - 1;
                msk &= msk - 1;
                int i = ig + (base + b) * 8;
                const float4* mi = mf4 + i * 4;    // L2-resident
                const float4* mj = mf4 + j * 4;
                float norm = 0.f;
#pragma unroll
                for (int pp = 0; pp < 4; ++pp) {
                    float4 a = mi[pp], bb = mj[pp];
                    norm += (fabsf(a.x - bb.x) + fabsf(a.y - bb.y)) +
                            (fabsf(a.z - bb.z) + fabsf(a.w - bb.w));
                }
                // fp32 absorption vs self-term 1.0: ex <= 2^-24 -> +0.0f
                float ex = __expf(-norm);
                float exa = __fadd_rn(__fadd_rn(1.0f, ex), -1.0f);
                atomicAdd(&out[j * OUT_W + IN_F + f], exa);   // both sides
                atomicAdd(&out[i * OUT_W + IN_F + f], exa);
            }
        }
    }
}

// ---------------------------------------------------------------------------
extern "C" void kernel_launch(void* const* d_in, const int* in_sizes, int n_in,
                              void* d_out, int out_size) {
    const float* X = (const float*)d_in[0];   // [512, 512]
    const float* T = (const float*)d_in[1];   // [512, 64, 16]
    float* out = (float*)d_out;               // [512, 576]

    // host-side attribute set (not a stream op; capture-safe, deterministic)
    cudaFuncSetAttribute(gemm_tc, cudaFuncAttributeMaxDynamicSharedMemorySize,
                         GEMM_SMEM_BYTES);

    gemm_tc<<<dim3(16, 8), 512, GEMM_SMEM_BYTES>>>(X, T, out);
    boundexp<<<dim3(OUT_F, 8), 256>>>(X, out);
}